// round 1
// baseline (speedup 1.0000x reference)
#include <cuda_runtime.h>
#include <math.h>

#define NF 128
#define HID 64
#define MAXN 50000
#define MAXE 800000
#define MAXG 64
#define BN_EPS 1e-5f
#define WPAD 72

// ---- static scratch (no allocations allowed) ----
__device__ float g_deg [MAXN];
__device__ float g_dinv[MAXN];
__device__ float g_norm[MAXE];
__device__ float g_id  [MAXN * HID];
__device__ float g_hp  [MAXN * HID];
__device__ float g_agg [MAXN * HID];
__device__ float g_h   [MAXN * HID];
__device__ float g_sums[MAXG * HID];
__device__ float g_cnts[MAXG];

__device__ __forceinline__ void red_add_v4(float* addr, float4 v) {
    asm volatile("red.global.add.v4.f32 [%0], {%1,%2,%3,%4};"
                 :: "l"(addr), "f"(v.x), "f"(v.y), "f"(v.z), "f"(v.w)
                 : "memory");
}

// ---------------- degree / norm ----------------
__global__ void k_init(int N, int G) {
    int i = blockIdx.x * blockDim.x + threadIdx.x;
    if (i < N) g_deg[i] = 1.0f;          // self loop
    if (i < G * HID) g_sums[i] = 0.0f;
    if (i < G) g_cnts[i] = 0.0f;
}

__global__ void k_count(const int* __restrict__ dst, int E) {
    int e = blockIdx.x * blockDim.x + threadIdx.x;
    if (e < E) atomicAdd(&g_deg[dst[e]], 1.0f);
}

__global__ void k_dinv(int N) {
    int i = blockIdx.x * blockDim.x + threadIdx.x;
    if (i < N) g_dinv[i] = rsqrtf(g_deg[i]);
}

__global__ void k_norm(const int* __restrict__ src, const int* __restrict__ dst, int E) {
    int e = blockIdx.x * blockDim.x + threadIdx.x;
    if (e < E) g_norm[e] = g_dinv[src[e]] * g_dinv[dst[e]];
}

// ---------------- GEMM: out[N,64] = X[N,K] @ W[64,K]^T ----------------
// 256 threads/block; block covers 64 nodes; thread (fg,nl) computes
// 4 nodes x 4 features. W transposed into smem (padded rows, 16B aligned).
template <int K>
__global__ void k_gemm(const float* __restrict__ X, const float* __restrict__ W,
                       float* __restrict__ out, int N) {
    __shared__ float Wt[K][WPAD];   // Wt[k][f] = W[f*K+k]
    const int tid = threadIdx.x;
    for (int idx = tid; idx < K * HID; idx += 256) {
        int f = idx / K;
        int k = idx - f * K;
        Wt[k][f] = W[idx];
    }
    __syncthreads();

    const int fg4 = (tid & 15) * 4;   // features [fg4, fg4+3]
    const int nl  = tid >> 4;         // 0..15
    const int nbase = blockIdx.x * 64;

    int  n[4];
    bool ok[4];
#pragma unroll
    for (int m = 0; m < 4; m++) { n[m] = nbase + m * 16 + nl; ok[m] = (n[m] < N); }

    float4 acc[4];
#pragma unroll
    for (int m = 0; m < 4; m++) acc[m] = make_float4(0.f, 0.f, 0.f, 0.f);

#define GEMM_STEP(J, COMP)                                              \
    {                                                                   \
        float4 w = *(const float4*)&Wt[k0 + J][fg4];                    \
        _Pragma("unroll")                                               \
        for (int m = 0; m < 4; m++) {                                   \
            float xs = xv[m].COMP;                                      \
            acc[m].x = fmaf(xs, w.x, acc[m].x);                         \
            acc[m].y = fmaf(xs, w.y, acc[m].y);                         \
            acc[m].z = fmaf(xs, w.z, acc[m].z);                         \
            acc[m].w = fmaf(xs, w.w, acc[m].w);                         \
        }                                                               \
    }

    for (int k0 = 0; k0 < K; k0 += 4) {
        float4 xv[4];
#pragma unroll
        for (int m = 0; m < 4; m++)
            xv[m] = ok[m] ? *(const float4*)(X + (size_t)n[m] * K + k0)
                          : make_float4(0.f, 0.f, 0.f, 0.f);
        GEMM_STEP(0, x)
        GEMM_STEP(1, y)
        GEMM_STEP(2, z)
        GEMM_STEP(3, w)
    }
#undef GEMM_STEP

#pragma unroll
    for (int m = 0; m < 4; m++)
        if (ok[m]) *(float4*)(out + (size_t)n[m] * HID + fg4) = acc[m];
}

// ---------------- zero agg ----------------
__global__ void k_zero_agg(int n4) {
    int i = blockIdx.x * blockDim.x + threadIdx.x;
    if (i < n4) ((float4*)g_agg)[i] = make_float4(0.f, 0.f, 0.f, 0.f);
}

// ---------------- edge scatter: agg[dst] += hp[src]*norm ----------------
__global__ void k_scatter(const int* __restrict__ src, const int* __restrict__ dst, int E) {
    int t = blockIdx.x * blockDim.x + threadIdx.x;
    int e = t >> 4;
    if (e >= E) return;
    int f = (t & 15) * 4;
    int s = src[e];
    int d = dst[e];
    float nv = g_norm[e];
    float4 v = *(const float4*)(g_hp + (size_t)s * HID + f);
    float4 mv = make_float4(v.x * nv, v.y * nv, v.z * nv, v.w * nv);
    red_add_v4(g_agg + (size_t)d * HID + f, mv);
}

// ---------------- epilogue: self-loop + bias + BN + relu + residual ----
// mode 0: residual = g_id; mode 1: residual = g_h; mode 2: none
__global__ void k_epilogue(const float* __restrict__ bias,
                           const float* __restrict__ gamma,
                           const float* __restrict__ beta,
                           const float* __restrict__ mean,
                           const float* __restrict__ var,
                           int mode, float* hout, int N) {
    int t = blockIdx.x * blockDim.x + threadIdx.x;
    int n = t >> 4;
    if (n >= N) return;
    int f = (t & 15) * 4;
    float di = g_dinv[n];
    float d2 = di * di;
    float4 a = *(const float4*)(g_agg + (size_t)n * HID + f);
    float4 p = *(const float4*)(g_hp  + (size_t)n * HID + f);
    float o[4];
    float av[4] = {a.x, a.y, a.z, a.w};
    float pv[4] = {p.x, p.y, p.z, p.w};
#pragma unroll
    for (int j = 0; j < 4; j++) {
        float v = av[j] + pv[j] * d2 + bias[f + j];
        float sc = gamma[f + j] * rsqrtf(var[f + j] + BN_EPS);
        v = (v - mean[f + j]) * sc + beta[f + j];
        o[j] = fmaxf(v, 0.f);
    }
    if (mode == 0) {
        float4 r = *(const float4*)(g_id + (size_t)n * HID + f);
        o[0] += r.x; o[1] += r.y; o[2] += r.z; o[3] += r.w;
    } else if (mode == 1) {
        float4 r = *(const float4*)(g_h + (size_t)n * HID + f);
        o[0] += r.x; o[1] += r.y; o[2] += r.z; o[3] += r.w;
    }
    *(float4*)(hout + (size_t)n * HID + f) = make_float4(o[0], o[1], o[2], o[3]);
}

// ---------------- global mean pool ----------------
__global__ void k_pool(const int* __restrict__ batch, int N) {
    int t = blockIdx.x * blockDim.x + threadIdx.x;
    int n = t >> 4;
    if (n >= N) return;
    int f = (t & 15) * 4;
    int g = batch[n];
    float4 v = *(const float4*)(g_hp + (size_t)n * HID + f);
    red_add_v4(&g_sums[(size_t)g * HID + f], v);
    if ((t & 15) == 0) atomicAdd(&g_cnts[g], 1.0f);
}

// ---------------- final linear ----------------
__global__ void k_final(const float* __restrict__ lin_w, const float* __restrict__ lin_b,
                        float* __restrict__ out, int G) {
    int g = blockIdx.x * blockDim.x + threadIdx.x;
    if (g >= G) return;
    float c = fmaxf(g_cnts[g], 1.0f);
    float acc = 0.f;
#pragma unroll
    for (int f = 0; f < HID; f++) acc += g_sums[g * HID + f] * lin_w[f];
    out[g] = acc / c + lin_b[0];
}

// ---------------- host launcher ----------------
extern "C" void kernel_launch(void* const* d_in, const int* in_sizes, int n_in,
                              void* d_out, int out_size) {
    const float* x     = (const float*)d_in[0];
    const int*   ei    = (const int*)  d_in[1];
    const int*   batch = (const int*)  d_in[2];
    const float* W_in  = (const float*)d_in[3];
    const float* W1    = (const float*)d_in[4];
    const float* b1    = (const float*)d_in[5];
    const float* Ws    = (const float*)d_in[6];
    const float* bs    = (const float*)d_in[7];
    const float* bn_g  = (const float*)d_in[8];
    const float* bn_b  = (const float*)d_in[9];
    const float* bn_m  = (const float*)d_in[10];
    const float* bn_v  = (const float*)d_in[11];
    const float* lin_w = (const float*)d_in[12];
    const float* lin_b = (const float*)d_in[13];
    float* out = (float*)d_out;

    const int N = in_sizes[0] / NF;
    const int E = in_sizes[1] / 2;
    const int G = out_size;
    const int* src = ei;
    const int* dst = ei + E;

    float *p_id, *p_hp, *p_h;
    cudaGetSymbolAddress((void**)&p_id, g_id);
    cudaGetSymbolAddress((void**)&p_hp, g_hp);
    cudaGetSymbolAddress((void**)&p_h,  g_h);

    const int thr = 256;
    int initN = N > G * HID ? N : G * HID;
    k_init <<<(initN + thr - 1) / thr, thr>>>(N, G);
    k_count<<<(E + thr - 1) / thr, thr>>>(dst, E);
    k_dinv <<<(N + thr - 1) / thr, thr>>>(N);
    k_norm <<<(E + thr - 1) / thr, thr>>>(src, dst, E);

    const int gemmB = (N + 63) / 64;
    k_gemm<NF><<<gemmB, 256>>>(x, W_in, p_id, N);
    k_gemm<NF><<<gemmB, 256>>>(x, W1,   p_hp, N);

    const int nodeT = N * 16;
    const int nodeB = (nodeT + thr - 1) / thr;
    const long edgeT = (long)E * 16;
    const int edgeB = (int)((edgeT + thr - 1) / thr);

    for (int layer = 0; layer < 5; layer++) {
        if (layer > 0)
            k_gemm<HID><<<gemmB, 256>>>(p_h, Ws + (size_t)(layer - 1) * HID * HID, p_hp, N);
        k_zero_agg<<<nodeB, thr>>>(nodeT);
        k_scatter <<<edgeB, thr>>>(src, dst, E);
        int mode = (layer == 0) ? 0 : (layer < 4 ? 1 : 2);
        const float* bias = (layer == 0) ? b1 : bs + (size_t)(layer - 1) * HID;
        float* hout = (layer < 4) ? p_h : p_hp;
        k_epilogue<<<nodeB, thr>>>(bias, bn_g + layer * HID, bn_b + layer * HID,
                                   bn_m + layer * HID, bn_v + layer * HID,
                                   mode, hout, N);
    }

    k_pool <<<nodeB, thr>>>(batch, N);
    k_final<<<1, ((G + 31) / 32) * 32>>>(lin_w, lin_b, out, G);
}

// round 2
// speedup vs baseline: 1.3827x; 1.3827x over previous
#include <cuda_runtime.h>
#include <math.h>

#define NF 128
#define HID 64
#define MAXN 50000
#define MAXE 800000
#define MAXG 64
#define BN_EPS 1e-5f
#define WPAD 72

// ---- static scratch ----
__device__ int    g_cnt   [MAXN];
__device__ int    g_rowptr[MAXN];
__device__ int    g_cursor[MAXN];
__device__ int    g_bsum  [64];
__device__ float  g_dinv  [MAXN];
__device__ float2 g_csr   [MAXE];          // (.x = src as int bits, .y = norm)
__device__ float  g_id    [MAXN * HID];
__device__ float  g_hp    [MAXN * HID];
__device__ float  g_h     [MAXN * HID];
__device__ float  g_sums  [MAXG * HID];
__device__ float  g_cnts  [MAXG];

__device__ __forceinline__ void red_add_v2(float* addr, float a, float b) {
    asm volatile("red.global.add.v2.f32 [%0], {%1,%2};"
                 :: "l"(addr), "f"(a), "f"(b) : "memory");
}

// ---------------- setup ----------------
__global__ void k_init(int N, int G) {
    int i = blockIdx.x * blockDim.x + threadIdx.x;
    if (i < N) g_cnt[i] = 0;
    if (i < G * HID) g_sums[i] = 0.0f;
    if (i < G) g_cnts[i] = 0.0f;
}

__global__ void k_hist(const int* __restrict__ dst, int E) {
    int e = blockIdx.x * blockDim.x + threadIdx.x;
    if (e < E) atomicAdd(&g_cnt[dst[e]], 1);
}

// per-block exclusive scan of g_cnt (1024 elements/block)
__global__ void k_scan1(int N) {
    __shared__ int sh[1024];
    int i = blockIdx.x * 1024 + threadIdx.x;
    int v = (i < N) ? g_cnt[i] : 0;
    sh[threadIdx.x] = v;
    __syncthreads();
    for (int off = 1; off < 1024; off <<= 1) {
        int t = (threadIdx.x >= off) ? sh[threadIdx.x - off] : 0;
        __syncthreads();
        sh[threadIdx.x] += t;
        __syncthreads();
    }
    if (i < N) g_rowptr[i] = sh[threadIdx.x] - v;   // exclusive within block
    if (threadIdx.x == 1023) g_bsum[blockIdx.x] = sh[1023];
}

__global__ void k_scan2(int nb) {
    if (threadIdx.x == 0) {
        int s = 0;
        for (int b = 0; b < nb; b++) { int t = g_bsum[b]; g_bsum[b] = s; s += t; }
    }
}

__global__ void k_scan3(int N) {
    int i = blockIdx.x * blockDim.x + threadIdx.x;
    if (i < N) {
        int r = g_rowptr[i] + g_bsum[i >> 10];
        g_rowptr[i] = r;
        g_cursor[i] = r;
        g_dinv[i]   = rsqrtf((float)g_cnt[i] + 1.0f);  // +1 self-loop
    }
}

__global__ void k_fill(const int* __restrict__ src, const int* __restrict__ dst, int E) {
    int e = blockIdx.x * blockDim.x + threadIdx.x;
    if (e < E) {
        int s = src[e], d = dst[e];
        int pos = atomicAdd(&g_cursor[d], 1);
        g_csr[pos] = make_float2(__int_as_float(s), g_dinv[s] * g_dinv[d]);
    }
}

// ---------------- GEMM: out[N,64] = X[N,K] @ W[64,K]^T ----------------
template <int K>
__global__ void __launch_bounds__(256) k_gemm(const float* __restrict__ X,
                                              const float* __restrict__ W,
                                              float* __restrict__ out, int N) {
    __shared__ float Wt[K][WPAD];   // Wt[k][f] = W[f*K+k]
    const int tid = threadIdx.x;
    for (int idx = tid; idx < K * HID; idx += 256) {
        int f = idx / K;
        int k = idx - f * K;
        Wt[k][f] = W[idx];
    }
    __syncthreads();

    const int fg4 = (tid & 15) * 4;
    const int nl  = tid >> 4;
    const int nbase = blockIdx.x * 64;

    int  n[4];
    bool ok[4];
#pragma unroll
    for (int m = 0; m < 4; m++) { n[m] = nbase + m * 16 + nl; ok[m] = (n[m] < N); }

    float4 acc[4];
#pragma unroll
    for (int m = 0; m < 4; m++) acc[m] = make_float4(0.f, 0.f, 0.f, 0.f);

#define GEMM_STEP(J, COMP)                                              \
    {                                                                   \
        float4 w = *(const float4*)&Wt[k0 + J][fg4];                    \
        _Pragma("unroll")                                               \
        for (int m = 0; m < 4; m++) {                                   \
            float xs = xv[m].COMP;                                      \
            acc[m].x = fmaf(xs, w.x, acc[m].x);                         \
            acc[m].y = fmaf(xs, w.y, acc[m].y);                         \
            acc[m].z = fmaf(xs, w.z, acc[m].z);                         \
            acc[m].w = fmaf(xs, w.w, acc[m].w);                         \
        }                                                               \
    }

    for (int k0 = 0; k0 < K; k0 += 4) {
        float4 xv[4];
#pragma unroll
        for (int m = 0; m < 4; m++)
            xv[m] = ok[m] ? *(const float4*)(X + (size_t)n[m] * K + k0)
                          : make_float4(0.f, 0.f, 0.f, 0.f);
        GEMM_STEP(0, x)
        GEMM_STEP(1, y)
        GEMM_STEP(2, z)
        GEMM_STEP(3, w)
    }
#undef GEMM_STEP

#pragma unroll
    for (int m = 0; m < 4; m++)
        if (ok[m]) *(float4*)(out + (size_t)n[m] * HID + fg4) = acc[m];
}

// ---------------- fused aggregate + epilogue (+ optional pool) -----------
// warp per node; lane owns 2 features. agg = sum_{e in CSR[n]} hp[src_e]*norm_e
// then + hp[n]*dinv^2 (self loop) + bias, BN, relu, + resid; store to hout
// (if non-null) and/or pool into g_sums (if batch non-null).
__global__ void __launch_bounds__(256) k_agg(
        const float* __restrict__ hp, const float* __restrict__ resid,
        const float* __restrict__ bias, const float* __restrict__ gamma,
        const float* __restrict__ beta, const float* __restrict__ mean,
        const float* __restrict__ var,
        float* __restrict__ hout, const int* __restrict__ batch, int N) {
    int n = (blockIdx.x * blockDim.x + threadIdx.x) >> 5;
    if (n >= N) return;
    const int lane = threadIdx.x & 31;
    const int f = lane * 2;

    const int start = g_rowptr[n];
    const int len   = g_cnt[n];

    float ax = 0.f, ay = 0.f;
    for (int base = 0; base < len; base += 32) {
        float2 ent = (base + lane < len) ? g_csr[start + base + lane]
                                         : make_float2(0.f, 0.f);
        int m = min(32, len - base);
#pragma unroll 4
        for (int j = 0; j < m; j++) {
            int   s  = __shfl_sync(0xffffffffu, __float_as_int(ent.x), j);
            float nv = __shfl_sync(0xffffffffu, ent.y, j);
            float2 v = *(const float2*)(hp + (size_t)s * HID + f);
            ax = fmaf(v.x, nv, ax);
            ay = fmaf(v.y, nv, ay);
        }
    }

    float di = g_dinv[n];
    float d2 = di * di;
    float2 p = *(const float2*)(hp + (size_t)n * HID + f);
    float vx = ax + p.x * d2 + bias[f];
    float vy = ay + p.y * d2 + bias[f + 1];
    vx = (vx - mean[f])     * (gamma[f]     * rsqrtf(var[f]     + BN_EPS)) + beta[f];
    vy = (vy - mean[f + 1]) * (gamma[f + 1] * rsqrtf(var[f + 1] + BN_EPS)) + beta[f + 1];
    vx = fmaxf(vx, 0.f);
    vy = fmaxf(vy, 0.f);
    if (resid) {
        float2 r = *(const float2*)(resid + (size_t)n * HID + f);
        vx += r.x; vy += r.y;
    }
    if (hout)
        *(float2*)(hout + (size_t)n * HID + f) = make_float2(vx, vy);
    if (batch) {
        int g = batch[n];
        red_add_v2(&g_sums[(size_t)g * HID + f], vx, vy);
        if (lane == 0) atomicAdd(&g_cnts[g], 1.0f);
    }
}

// ---------------- final linear ----------------
__global__ void k_final(const float* __restrict__ lin_w, const float* __restrict__ lin_b,
                        float* __restrict__ out, int G) {
    int g = blockIdx.x * blockDim.x + threadIdx.x;
    if (g >= G) return;
    float c = fmaxf(g_cnts[g], 1.0f);
    float acc = 0.f;
#pragma unroll
    for (int f = 0; f < HID; f++) acc += g_sums[g * HID + f] * lin_w[f];
    out[g] = acc / c + lin_b[0];
}

// ---------------- host launcher ----------------
extern "C" void kernel_launch(void* const* d_in, const int* in_sizes, int n_in,
                              void* d_out, int out_size) {
    const float* x     = (const float*)d_in[0];
    const int*   ei    = (const int*)  d_in[1];
    const int*   batch = (const int*)  d_in[2];
    const float* W_in  = (const float*)d_in[3];
    const float* W1    = (const float*)d_in[4];
    const float* b1    = (const float*)d_in[5];
    const float* Ws    = (const float*)d_in[6];
    const float* bs    = (const float*)d_in[7];
    const float* bn_g  = (const float*)d_in[8];
    const float* bn_b  = (const float*)d_in[9];
    const float* bn_m  = (const float*)d_in[10];
    const float* bn_v  = (const float*)d_in[11];
    const float* lin_w = (const float*)d_in[12];
    const float* lin_b = (const float*)d_in[13];
    float* out = (float*)d_out;

    const int N = in_sizes[0] / NF;
    const int E = in_sizes[1] / 2;
    const int G = out_size;
    const int* src = ei;
    const int* dst = ei + E;

    float *p_id, *p_hp, *p_h;
    cudaGetSymbolAddress((void**)&p_id, g_id);
    cudaGetSymbolAddress((void**)&p_hp, g_hp);
    cudaGetSymbolAddress((void**)&p_h,  g_h);

    const int thr = 256;
    int initN = N > G * HID ? N : G * HID;
    k_init <<<(initN + thr - 1) / thr, thr>>>(N, G);
    k_hist <<<(E + thr - 1) / thr, thr>>>(dst, E);
    int nb = (N + 1023) / 1024;
    k_scan1<<<nb, 1024>>>(N);
    k_scan2<<<1, 32>>>(nb);
    k_scan3<<<(N + thr - 1) / thr, thr>>>(N);
    k_fill <<<(E + thr - 1) / thr, thr>>>(src, dst, E);

    const int gemmB = (N + 63) / 64;
    k_gemm<NF><<<gemmB, 256>>>(x, W_in, p_id, N);
    k_gemm<NF><<<gemmB, 256>>>(x, W1,   p_hp, N);

    const int aggB = (N * 32 + thr - 1) / thr;

    for (int layer = 0; layer < 5; layer++) {
        if (layer > 0)
            k_gemm<HID><<<gemmB, 256>>>(p_h, Ws + (size_t)(layer - 1) * HID * HID, p_hp, N);
        const float* bias  = (layer == 0) ? b1 : bs + (size_t)(layer - 1) * HID;
        const float* resid = (layer == 0) ? p_id : (layer < 4 ? p_h : nullptr);
        float*       hout  = (layer < 4) ? p_h : nullptr;
        const int*   bptr  = (layer == 4) ? batch : nullptr;
        k_agg<<<aggB, thr>>>(p_hp, resid, bias,
                             bn_g + layer * HID, bn_b + layer * HID,
                             bn_m + layer * HID, bn_v + layer * HID,
                             hout, bptr, N);
    }

    k_final<<<1, ((G + 31) / 32) * 32>>>(lin_w, lin_b, out, G);
}

// round 3
// speedup vs baseline: 1.4537x; 1.0514x over previous
#include <cuda_runtime.h>
#include <cuda_fp16.h>
#include <math.h>

#define NF 128
#define HID 64
#define MAXN 50000
#define MAXE 800000
#define MAXG 64
#define BN_EPS 1e-5f
#define WPAD 72

// ---- static scratch ----
__device__ int    g_cnt   [MAXN];
__device__ int    g_rowptr[MAXN];
__device__ int    g_cursor[MAXN];
__device__ int    g_bsum  [64];
__device__ float  g_dinv  [MAXN];
__device__ int    g_csr   [MAXE];          // src indices grouped by dst
__device__ float  g_id    [MAXN * HID];    // fp32 input projection (residual)
__device__ __half g_hph   [MAXN * HID];    // fp16 pre-scaled GEMM output
__device__ float  g_h     [MAXN * HID];    // fp32 layer state
__device__ float  g_sums  [MAXG * HID];
__device__ float  g_cnts  [MAXG];

__device__ __forceinline__ void red_add_v2(float* addr, float a, float b) {
    asm volatile("red.global.add.v2.f32 [%0], {%1,%2};"
                 :: "l"(addr), "f"(a), "f"(b) : "memory");
}

// ---------------- setup ----------------
__global__ void k_init(int N, int G) {
    int i = blockIdx.x * blockDim.x + threadIdx.x;
    if (i < N) g_cnt[i] = 0;
    if (i < G * HID) g_sums[i] = 0.0f;
    if (i < G) g_cnts[i] = 0.0f;
}

__global__ void k_hist(const int* __restrict__ dst, int E) {
    int e = blockIdx.x * blockDim.x + threadIdx.x;
    if (e < E) atomicAdd(&g_cnt[dst[e]], 1);
}

// per-block exclusive scan of g_cnt (1024 elements/block)
__global__ void k_scan1(int N) {
    __shared__ int sh[1024];
    int i = blockIdx.x * 1024 + threadIdx.x;
    int v = (i < N) ? g_cnt[i] : 0;
    sh[threadIdx.x] = v;
    __syncthreads();
    for (int off = 1; off < 1024; off <<= 1) {
        int t = (threadIdx.x >= off) ? sh[threadIdx.x - off] : 0;
        __syncthreads();
        sh[threadIdx.x] += t;
        __syncthreads();
    }
    if (i < N) g_rowptr[i] = sh[threadIdx.x] - v;   // exclusive within block
    if (threadIdx.x == 1023) g_bsum[blockIdx.x] = sh[1023];
}

// parallel exclusive scan of <=64 block sums
__global__ void k_scan2(int nb) {
    __shared__ int sh[64];
    int i = threadIdx.x;
    int v = (i < nb) ? g_bsum[i] : 0;
    sh[i] = v;
    __syncthreads();
    for (int off = 1; off < 64; off <<= 1) {
        int t = (i >= off) ? sh[i - off] : 0;
        __syncthreads();
        sh[i] += t;
        __syncthreads();
    }
    if (i < nb) g_bsum[i] = sh[i] - v;
}

__global__ void k_scan3(int N) {
    int i = blockIdx.x * blockDim.x + threadIdx.x;
    if (i < N) {
        int r = g_rowptr[i] + g_bsum[i >> 10];
        g_rowptr[i] = r;
        g_cursor[i] = r;
        g_dinv[i]   = rsqrtf((float)g_cnt[i] + 1.0f);  // +1 self-loop
    }
}

__global__ void k_fill(const int* __restrict__ src, const int* __restrict__ dst, int E) {
    int e = blockIdx.x * blockDim.x + threadIdx.x;
    if (e < E) {
        int d = dst[e];
        int pos = atomicAdd(&g_cursor[d], 1);
        g_csr[pos] = src[e];
    }
}

// ---------------- GEMM: out[N,64] = X[N,K] @ W[64,K]^T ----------------
// HOUT: write fp16 scaled by dinv[n] (for gather); else fp32 raw.
template <int K, bool HOUT>
__global__ void __launch_bounds__(256) k_gemm(const float* __restrict__ X,
                                              const float* __restrict__ W,
                                              void* __restrict__ outp, int N) {
    __shared__ float Wt[K][WPAD];   // Wt[k][f] = W[f*K+k]
    const int tid = threadIdx.x;
    for (int idx = tid; idx < K * HID; idx += 256) {
        int f = idx / K;
        int k = idx - f * K;
        Wt[k][f] = W[idx];
    }
    __syncthreads();

    const int fg4 = (tid & 15) * 4;
    const int nl  = tid >> 4;
    const int nbase = blockIdx.x * 64;

    int  n[4];
    bool ok[4];
#pragma unroll
    for (int m = 0; m < 4; m++) { n[m] = nbase + m * 16 + nl; ok[m] = (n[m] < N); }

    float4 acc[4];
#pragma unroll
    for (int m = 0; m < 4; m++) acc[m] = make_float4(0.f, 0.f, 0.f, 0.f);

#define GEMM_STEP(J, COMP)                                              \
    {                                                                   \
        float4 w = *(const float4*)&Wt[k0 + J][fg4];                    \
        _Pragma("unroll")                                               \
        for (int m = 0; m < 4; m++) {                                   \
            float xs = xv[m].COMP;                                      \
            acc[m].x = fmaf(xs, w.x, acc[m].x);                         \
            acc[m].y = fmaf(xs, w.y, acc[m].y);                         \
            acc[m].z = fmaf(xs, w.z, acc[m].z);                         \
            acc[m].w = fmaf(xs, w.w, acc[m].w);                         \
        }                                                               \
    }

    for (int k0 = 0; k0 < K; k0 += 4) {
        float4 xv[4];
#pragma unroll
        for (int m = 0; m < 4; m++)
            xv[m] = ok[m] ? *(const float4*)(X + (size_t)n[m] * K + k0)
                          : make_float4(0.f, 0.f, 0.f, 0.f);
        GEMM_STEP(0, x)
        GEMM_STEP(1, y)
        GEMM_STEP(2, z)
        GEMM_STEP(3, w)
    }
#undef GEMM_STEP

#pragma unroll
    for (int m = 0; m < 4; m++) {
        if (!ok[m]) continue;
        if (HOUT) {
            float s = g_dinv[n[m]];
            __half2 a = __floats2half2_rn(acc[m].x * s, acc[m].y * s);
            __half2 b = __floats2half2_rn(acc[m].z * s, acc[m].w * s);
            __half2* o = (__half2*)((__half*)outp + (size_t)n[m] * HID + fg4);
            o[0] = a; o[1] = b;
        } else {
            *(float4*)((float*)outp + (size_t)n[m] * HID + fg4) = acc[m];
        }
    }
}

// ---------------- fused aggregate + epilogue (+ optional pool) -----------
// warp per node; lane owns 2 features.
// out[n] = relu(BN( dinv[n]*(sum_{e} hpS[src_e] + hpS[n]) + bias )) (+resid)
__global__ void __launch_bounds__(256) k_agg(
        const __half* __restrict__ hp, const float* __restrict__ resid,
        const float* __restrict__ bias, const float* __restrict__ gamma,
        const float* __restrict__ beta, const float* __restrict__ mean,
        const float* __restrict__ var,
        float* __restrict__ hout, const int* __restrict__ batch, int N) {
    int n = (blockIdx.x * blockDim.x + threadIdx.x) >> 5;
    if (n >= N) return;
    const int lane = threadIdx.x & 31;
    const int f = lane * 2;

    const int  start = g_rowptr[n];
    const int  len   = g_cnt[n];
    const int* cs    = g_csr + start;

    float ax = 0.f, ay = 0.f, bx = 0.f, by = 0.f;
    int j = 0;
    for (; j + 4 <= len; j += 4) {
        int s0 = cs[j], s1 = cs[j + 1], s2 = cs[j + 2], s3 = cs[j + 3];
        float2 v0 = __half22float2(*(const __half2*)(hp + (size_t)s0 * HID + f));
        float2 v1 = __half22float2(*(const __half2*)(hp + (size_t)s1 * HID + f));
        float2 v2 = __half22float2(*(const __half2*)(hp + (size_t)s2 * HID + f));
        float2 v3 = __half22float2(*(const __half2*)(hp + (size_t)s3 * HID + f));
        ax += v0.x + v1.x;
        ay += v0.y + v1.y;
        bx += v2.x + v3.x;
        by += v2.y + v3.y;
    }
    for (; j < len; j++) {
        int s = cs[j];
        float2 v = __half22float2(*(const __half2*)(hp + (size_t)s * HID + f));
        ax += v.x;
        ay += v.y;
    }
    ax += bx; ay += by;

    float di = g_dinv[n];
    float2 p = __half22float2(*(const __half2*)(hp + (size_t)n * HID + f));
    float vx = (ax + p.x) * di + bias[f];
    float vy = (ay + p.y) * di + bias[f + 1];
    vx = (vx - mean[f])     * (gamma[f]     * rsqrtf(var[f]     + BN_EPS)) + beta[f];
    vy = (vy - mean[f + 1]) * (gamma[f + 1] * rsqrtf(var[f + 1] + BN_EPS)) + beta[f + 1];
    vx = fmaxf(vx, 0.f);
    vy = fmaxf(vy, 0.f);
    if (resid) {
        float2 r = *(const float2*)(resid + (size_t)n * HID + f);
        vx += r.x; vy += r.y;
    }
    if (hout)
        *(float2*)(hout + (size_t)n * HID + f) = make_float2(vx, vy);
    if (batch) {
        int g = batch[n];
        red_add_v2(&g_sums[(size_t)g * HID + f], vx, vy);
        if (lane == 0) atomicAdd(&g_cnts[g], 1.0f);
    }
}

// ---------------- final linear ----------------
__global__ void k_final(const float* __restrict__ lin_w, const float* __restrict__ lin_b,
                        float* __restrict__ out, int G) {
    int g = blockIdx.x * blockDim.x + threadIdx.x;
    if (g >= G) return;
    float c = fmaxf(g_cnts[g], 1.0f);
    float acc = 0.f;
#pragma unroll
    for (int f = 0; f < HID; f++) acc += g_sums[g * HID + f] * lin_w[f];
    out[g] = acc / c + lin_b[0];
}

// ---------------- host launcher ----------------
extern "C" void kernel_launch(void* const* d_in, const int* in_sizes, int n_in,
                              void* d_out, int out_size) {
    const float* x     = (const float*)d_in[0];
    const int*   ei    = (const int*)  d_in[1];
    const int*   batch = (const int*)  d_in[2];
    const float* W_in  = (const float*)d_in[3];
    const float* W1    = (const float*)d_in[4];
    const float* b1    = (const float*)d_in[5];
    const float* Ws    = (const float*)d_in[6];
    const float* bs    = (const float*)d_in[7];
    const float* bn_g  = (const float*)d_in[8];
    const float* bn_b  = (const float*)d_in[9];
    const float* bn_m  = (const float*)d_in[10];
    const float* bn_v  = (const float*)d_in[11];
    const float* lin_w = (const float*)d_in[12];
    const float* lin_b = (const float*)d_in[13];
    float* out = (float*)d_out;

    const int N = in_sizes[0] / NF;
    const int E = in_sizes[1] / 2;
    const int G = out_size;
    const int* src = ei;
    const int* dst = ei + E;

    float  *p_id, *p_h;
    __half *p_hph;
    cudaGetSymbolAddress((void**)&p_id,  g_id);
    cudaGetSymbolAddress((void**)&p_hph, g_hph);
    cudaGetSymbolAddress((void**)&p_h,   g_h);

    const int thr = 256;
    int initN = N > G * HID ? N : G * HID;
    k_init <<<(initN + thr - 1) / thr, thr>>>(N, G);
    k_hist <<<(E + thr - 1) / thr, thr>>>(dst, E);
    int nb = (N + 1023) / 1024;
    k_scan1<<<nb, 1024>>>(N);
    k_scan2<<<1, 64>>>(nb);
    k_scan3<<<(N + thr - 1) / thr, thr>>>(N);
    k_fill <<<(E + thr - 1) / thr, thr>>>(src, dst, E);

    const int gemmB = (N + 63) / 64;
    k_gemm<NF, false><<<gemmB, 256>>>(x, W_in, p_id,  N);   // residual proj, fp32
    k_gemm<NF, true ><<<gemmB, 256>>>(x, W1,   p_hph, N);   // layer-1, fp16 scaled

    const int aggB = (N * 32 + thr - 1) / thr;

    for (int layer = 0; layer < 5; layer++) {
        if (layer > 0)
            k_gemm<HID, true><<<gemmB, 256>>>(p_h, Ws + (size_t)(layer - 1) * HID * HID,
                                              p_hph, N);
        const float* bias  = (layer == 0) ? b1 : bs + (size_t)(layer - 1) * HID;
        const float* resid = (layer == 0) ? p_id : (layer < 4 ? p_h : nullptr);
        float*       hout  = (layer < 4) ? p_h : nullptr;
        const int*   bptr  = (layer == 4) ? batch : nullptr;
        k_agg<<<aggB, thr>>>(p_hph, resid, bias,
                             bn_g + layer * HID, bn_b + layer * HID,
                             bn_m + layer * HID, bn_v + layer * HID,
                             hout, bptr, N);
    }

    k_final<<<1, ((G + 31) / 32) * 32>>>(lin_w, lin_b, out, G);
}